// round 13
// baseline (speedup 1.0000x reference)
#include <cuda_runtime.h>
#include <cstdint>

// ---------------------------------------------------------------------------
// Problem constants
// ---------------------------------------------------------------------------
#define B_SZ   2
#define T_SZ   2048
#define C_SZ   2048
#define NH     16
#define NKV    4
#define HD     128
#define KVD    (NKV*HD)      // 512
#define MROWS  (B_SZ*T_SZ)   // 4096

// Scratch buffers (allocation-free rule: __device__ globals)
__device__ float g_q[MROWS * C_SZ];
__device__ float g_k[MROWS * KVD];
__device__ float g_vt[KVD * MROWS];    // V transposed: [kv_dim][b*T]
__device__ float g_y[MROWS * C_SZ];
__device__ float g_invf[64];
__device__ float2 g_cs[T_SZ * 64];     // rope cos/sin table

#define DEV __device__ __forceinline__

DEV uint32_t f2tf(float f) {
    uint32_t u;
    asm("cvt.rna.tf32.f32 %0, %1;" : "=r"(u) : "f"(f));
    return u;
}
DEV uint32_t f2tf_u(uint32_t x) {      // tf32 conversion of a raw f32 bit pattern
    uint32_t u;
    asm("cvt.rna.tf32.f32 %0, %1;" : "=r"(u) : "f"(__uint_as_float(x)));
    return u;
}

DEV void mma_tf32(float* d, const uint32_t* a, const uint32_t* b) {
    asm volatile(
        "mma.sync.aligned.m16n8k8.row.col.f32.tf32.tf32.f32 "
        "{%0,%1,%2,%3}, {%4,%5,%6,%7}, {%8,%9}, {%0,%1,%2,%3};\n"
        : "+f"(d[0]), "+f"(d[1]), "+f"(d[2]), "+f"(d[3])
        : "r"(a[0]), "r"(a[1]), "r"(a[2]), "r"(a[3]),
          "r"(b[0]), "r"(b[1]));
}

DEV uint32_t smem_u32(const void* p) {
    uint32_t a;
    asm("{ .reg .u64 t; cvta.to.shared.u64 t, %1; cvt.u32.u64 %0, t; }"
        : "=r"(a) : "l"(p));
    return a;
}

// ldmatrix x4 (b16 view — pure bit movement)
DEV void ldm4(uint32_t* r, uint32_t addr) {
    asm volatile("ldmatrix.sync.aligned.m8n8.x4.shared.b16 {%0,%1,%2,%3}, [%4];"
                 : "=r"(r[0]), "=r"(r[1]), "=r"(r[2]), "=r"(r[3]) : "r"(addr));
}
// ldmatrix + tf32 round (numerically identical to converting before the store)
DEV void ldm4cvt(uint32_t* r, uint32_t addr) {
    ldm4(r, addr);
    r[0] = f2tf_u(r[0]); r[1] = f2tf_u(r[1]);
    r[2] = f2tf_u(r[2]); r[3] = f2tf_u(r[3]);
}

// A-fragment tile addressing: 16 rows x 8 f32-cols starting at `tile` (byte addr).
DEV uint32_t a_addr(uint32_t tile, uint32_t ldb) {
    int l = threadIdx.x & 31;
    return tile + (uint32_t)((l & 7) + ((l >> 3) & 1) * 8) * ldb
                + (uint32_t)(l >> 4) * 16;
}
// B-fragment tile addressing (storage [n][k]): 16 n-rows x 8 f32 k-cols.
DEV uint32_t b_addr(uint32_t tile, uint32_t ldb) {
    int l = threadIdx.x & 31;
    return tile + (uint32_t)((l & 7) + (l >> 4) * 8) * ldb
                + (uint32_t)((l >> 3) & 1) * 16;
}

DEV void sts_v4(uint32_t addr, uint32_t x, uint32_t y, uint32_t z, uint32_t w) {
    asm volatile("st.shared.v4.b32 [%0], {%1,%2,%3,%4};"
                 :: "r"(addr), "r"(x), "r"(y), "r"(z), "r"(w) : "memory");
}

DEV void cp16(uint32_t dst, const void* src) {
    asm volatile("cp.async.cg.shared.global [%0], [%1], 16;"
                 :: "r"(dst), "l"(src) : "memory");
}
#define CP_COMMIT() asm volatile("cp.async.commit_group;" ::: "memory")
#define CP_WAIT1()  asm volatile("cp.async.wait_group 1;" ::: "memory")

// ---------------------------------------------------------------------------
// init kernels: inv_freq (fp64, identical numerics) + rope cos/sin table
// ---------------------------------------------------------------------------
__global__ void init_invf() {
    int i = threadIdx.x;
    if (i < 64) {
        const double LG = 9.210340371976184;   // ln(10000)
        g_invf[i] = (float)exp(-(double)i * (LG / 64.0));
    }
}

__global__ void init_cs() {
    int t = blockIdx.x, i = threadIdx.x;   // 64 threads
    float a = (float)t * g_invf[i];
    g_cs[t * 64 + i] = make_float2(cosf(a), sinf(a));
}

// ---------------------------------------------------------------------------
// NT GEMM: C[M,N] = A[M,K] * W[N,K]^T  (tf32 mma + ldmatrix fragments)
// Block tile 256x128x32, 8 warps 4x2 -> warp tile 64x64.
// cp.async 3-stage pipeline: smem holds raw f32; tf32 rounding applied after
// ldmatrix (identical numerics). One __syncthreads per K-tile.
// blockIdx.z selects (W0,C0,normal) vs (W1,C1,transposed-epilogue).
// ---------------------------------------------------------------------------
#define BM 256
#define BN 128
#define BK 32
#define G_LD    (BK + 4)                 // 36 words = 144 B rows
#define A_TILE  (BM * G_LD)
#define B_TILE  (BN * G_LD)
#define STG_W   (A_TILE + B_TILE)        // words per stage (13824)
#define NSTG    3
#define GEMM_SMEM_BYTES (NSTG * STG_W * 4)   // 165888 B

__global__ __launch_bounds__(256, 1)
void gemm_nt(const float* __restrict__ A,
             const float* __restrict__ W0, const float* __restrict__ W1,
             float* __restrict__ C0, float* __restrict__ C1,
             int N, int K, int ldT) {
    extern __shared__ uint32_t smg[];

    const float* W = blockIdx.z ? W1 : W0;
    float* C       = blockIdx.z ? C1 : C0;
    const int transC = blockIdx.z ? 1 : 0;

    const int tid  = threadIdx.x;
    const int warp = tid >> 5, lane = tid & 31;
    const int g = lane >> 2, tg = lane & 3;
    const int wm = (warp >> 1) * 64;
    const int wn = (warp & 1) * 64;
    const int m0 = blockIdx.y * BM, n0 = blockIdx.x * BN;

    const int lr = tid >> 3;                 // 0..31
    const int lc = (tid & 7) * 4;            // 0..28

    const uint32_t sbase = smem_u32(smg);
    const float* Ab = A + (size_t)m0 * K + lc;
    const float* Wb = W + (size_t)n0 * K + lc;

    float acc[4][8][4];
#pragma unroll
    for (int mi = 0; mi < 4; mi++)
#pragma unroll
        for (int nf = 0; nf < 8; nf++)
#pragma unroll
            for (int i = 0; i < 4; i++) acc[mi][nf][i] = 0.f;

    const int niter = K / BK;

    // stage issue: 8 A cp16 + 4 B cp16 per thread
    auto issue = [&](int it) {
        const uint32_t sb = sbase + (uint32_t)(it % NSTG) * (STG_W * 4);
        const int koff = it * BK;
#pragma unroll
        for (int i = 0; i < 8; i++) {
            int r = lr + i * 32;
            cp16(sb + (uint32_t)(r * G_LD + lc) * 4, Ab + (size_t)r * K + koff);
        }
#pragma unroll
        for (int i = 0; i < 4; i++) {
            int r = lr + i * 32;
            cp16(sb + (uint32_t)(A_TILE + r * G_LD + lc) * 4, Wb + (size_t)r * K + koff);
        }
    };

    // prologue: stages 0 and 1 in flight
    issue(0); CP_COMMIT();
    issue(1); CP_COMMIT();

    for (int it = 0; it < niter; it++) {
        CP_WAIT1();          // this thread's stage `it` group complete
        __syncthreads();     // all threads' stage `it` complete; buf (it+2)%3 free

        if (it + 2 < niter) issue(it + 2);
        CP_COMMIT();         // unconditional commit keeps wait_group accounting exact

        const uint32_t sb = sbase + (uint32_t)(it % NSTG) * (STG_W * 4);
        const uint32_t sAbyte = sb;
        const uint32_t sBbyte = sb + A_TILE * 4;
#pragma unroll
        for (int kk = 0; kk < 4; kk++) {
            uint32_t av[4][4];
#pragma unroll
            for (int mi = 0; mi < 4; mi++)
                ldm4cvt(av[mi], a_addr(sAbyte + (uint32_t)(wm + 16 * mi) * (G_LD * 4)
                                       + kk * 32, G_LD * 4));
#pragma unroll
            for (int nfp = 0; nfp < 4; nfp++) {
                uint32_t b[4];
                ldm4cvt(b, b_addr(sBbyte + (uint32_t)(wn + 16 * nfp) * (G_LD * 4)
                                  + kk * 32, G_LD * 4));
#pragma unroll
                for (int mi = 0; mi < 4; mi++) {
                    mma_tf32(acc[mi][2 * nfp],     av[mi], b);
                    mma_tf32(acc[mi][2 * nfp + 1], av[mi], b + 2);
                }
            }
        }
        __syncthreads();     // all warps done reading stage `it` before reuse
    }

    if (!transC) {
#pragma unroll
        for (int mi = 0; mi < 4; mi++) {
            int r0 = m0 + wm + mi * 16 + g;
#pragma unroll
            for (int nf = 0; nf < 8; nf++) {
                int c0 = n0 + wn + nf * 8 + 2 * tg;
                C[(size_t)r0 * N + c0]           = acc[mi][nf][0];
                C[(size_t)r0 * N + c0 + 1]       = acc[mi][nf][1];
                C[(size_t)(r0 + 8) * N + c0]     = acc[mi][nf][2];
                C[(size_t)(r0 + 8) * N + c0 + 1] = acc[mi][nf][3];
            }
        }
    } else {
        // transposed epilogue: Ct[n][m], ldT = MROWS
#pragma unroll
        for (int mi = 0; mi < 4; mi++) {
            int r0 = m0 + wm + mi * 16 + g;
#pragma unroll
            for (int nf = 0; nf < 8; nf++) {
                int c0 = n0 + wn + nf * 8 + 2 * tg;
                C[(size_t)c0 * ldT + r0]           = acc[mi][nf][0];
                C[(size_t)(c0 + 1) * ldT + r0]     = acc[mi][nf][1];
                C[(size_t)c0 * ldT + r0 + 8]       = acc[mi][nf][2];
                C[(size_t)(c0 + 1) * ldT + r0 + 8] = acc[mi][nf][3];
            }
        }
    }
}

// ---------------------------------------------------------------------------
// Fused per-head RMSNorm + RoPE for q and k (in place). cos/sin from table.
// ---------------------------------------------------------------------------
__global__ void normrope(float* __restrict__ q, float* __restrict__ k) {
    int w = (blockIdx.x * blockDim.x + threadIdx.x) >> 5;
    int lane = threadIdx.x & 31;
    const int QW = MROWS * NH;
    float* base;
    int t;
    if (w < QW) {
        int row = w / NH, h = w % NH;
        base = q + (size_t)row * C_SZ + h * HD;
        t = row % T_SZ;
    } else {
        int w2 = w - QW;
        if (w2 >= MROWS * NKV) return;
        int row = w2 / NKV, h = w2 % NKV;
        base = k + (size_t)row * KVD + h * HD;
        t = row % T_SZ;
    }
    float x0 = base[lane], x1 = base[lane + 32], x2 = base[lane + 64], x3 = base[lane + 96];
    float ss = x0 * x0 + x1 * x1 + x2 * x2 + x3 * x3;
#pragma unroll
    for (int o = 16; o; o >>= 1) ss += __shfl_xor_sync(0xffffffffu, ss, o);
    float rn = rsqrtf(ss * (1.0f / 128.0f) + 1.1920928955078125e-7f);
    x0 *= rn; x1 *= rn; x2 *= rn; x3 *= rn;

    float2 cs0 = g_cs[t * 64 + lane];
    float2 cs1 = g_cs[t * 64 + lane + 32];
    float c0 = cs0.x, s0 = cs0.y;
    float c1 = cs1.x, s1 = cs1.y;

    base[lane]      =  x0 * c0 + x2 * s0;
    base[lane + 64] = -x0 * s0 + x2 * c0;
    base[lane + 32] =  x1 * c1 + x3 * s1;
    base[lane + 96] = -x1 * s1 + x3 * c1;
}

// ---------------------------------------------------------------------------
// Flash attention, causal, GQA (group=4). Br=128, Bc=64, D=128.
// 8 warps; warp w owns rows [16w,16w+16). tf32 mma + ldmatrix fragments.
// V consumed pre-transposed. K/V double-buffered through registers.
// Block order reversed: longest (largest q0) causal blocks launch first.
// ---------------------------------------------------------------------------
#define SQ_LD 132
#define SVT_LD 68
#define SP_LD 68
#define OFF_Q 0
#define OFF_K (128 * SQ_LD)
#define OFF_VT (OFF_K + 64 * SQ_LD)
#define OFF_P (OFF_VT + 128 * SVT_LD)
#define ATTN_SMEM_WORDS (OFF_P + 128 * SP_LD)
#define ATTN_SMEM_BYTES (ATTN_SMEM_WORDS * 4)

__global__ __launch_bounds__(256, 1)
void attn_kernel(const float* __restrict__ q, const float* __restrict__ k,
                 const float* __restrict__ vt, float* __restrict__ y) {
    extern __shared__ uint32_t sm[];
    uint32_t* sQ  = sm + OFF_Q;
    uint32_t* sK  = sm + OFF_K;
    uint32_t* sVt = sm + OFF_VT;
    uint32_t* sP  = sm + OFF_P;

    const int tid = threadIdx.x, warp = tid >> 5, lane = tid & 31;
    const int g = lane >> 2, tg = lane & 3;
    const int q0 = (int)(gridDim.x - 1 - blockIdx.x) * 128;
    const int h = blockIdx.y, b = blockIdx.z;
    const int kvh = h >> 2;

    const float* qb = q + (size_t)b * T_SZ * C_SZ + (size_t)h * HD;
    const float* kb = k + (size_t)b * T_SZ * KVD + (size_t)kvh * HD;
    const float* vbt = vt + (size_t)(kvh * HD) * MROWS + (size_t)b * T_SZ;
    float*       yb = y + (size_t)b * T_SZ * C_SZ + (size_t)h * HD;

    const uint32_t sQb  = smem_u32(sQ);
    const uint32_t sKb  = smem_u32(sK);
    const uint32_t sVtb = smem_u32(sVt);
    const uint32_t sPb  = smem_u32(sP);

    float4 rk[8], rv[8];
#pragma unroll
    for (int i = 0; i < 8; i++) {
        int f = tid + i * 256;
        int r = f >> 5, c = (f & 31) * 4;
        rk[i] = *(const float4*)&kb[(size_t)r * KVD + c];
    }
#pragma unroll
    for (int i = 0; i < 8; i++) {
        int f = tid + i * 256;
        int r = f >> 4, c = (f & 15) * 4;
        rv[i] = *(const float4*)&vbt[(size_t)r * MROWS + c];
    }

#pragma unroll
    for (int i = 0; i < 16; i++) {
        int f = tid + i * 256;
        int r = f >> 5, c = (f & 31) * 4;
        float4 v4 = *(const float4*)&qb[(size_t)(q0 + r) * C_SZ + c];
        uint32_t* d = &sQ[r * SQ_LD + c];
        d[0] = f2tf(v4.x); d[1] = f2tf(v4.y); d[2] = f2tf(v4.z); d[3] = f2tf(v4.w);
    }

    float oacc[16][4];
#pragma unroll
    for (int nf = 0; nf < 16; nf++)
#pragma unroll
        for (int i = 0; i < 4; i++) oacc[nf][i] = 0.f;
    float m0r = -1e30f, m1r = -1e30f, l0r = 0.f, l1r = 0.f;

    const int wr = warp * 16;
    const int ntiles = q0 / 64 + 2;
    const float scale = 0.08838834764831845f;

    for (int j = 0; j < ntiles; j++) {
        const int k0 = j * 64;
        __syncthreads();

#pragma unroll
        for (int i = 0; i < 8; i++) {
            int f = tid + i * 256;
            int r = f >> 5, c = (f & 31) * 4;
            sts_v4(sKb + (uint32_t)(r * SQ_LD + c) * 4,
                   f2tf(rk[i].x), f2tf(rk[i].y), f2tf(rk[i].z), f2tf(rk[i].w));
        }
#pragma unroll
        for (int i = 0; i < 8; i++) {
            int f = tid + i * 256;
            int r = f >> 4, c = (f & 15) * 4;
            sts_v4(sVtb + (uint32_t)(r * SVT_LD + c) * 4,
                   f2tf(rv[i].x), f2tf(rv[i].y), f2tf(rv[i].z), f2tf(rv[i].w));
        }
        __syncthreads();

        if (j + 1 < ntiles) {
            const int k0n = k0 + 64;
#pragma unroll
            for (int i = 0; i < 8; i++) {
                int f = tid + i * 256;
                int r = f >> 5, c = (f & 31) * 4;
                rk[i] = *(const float4*)&kb[(size_t)(k0n + r) * KVD + c];
            }
#pragma unroll
            for (int i = 0; i < 8; i++) {
                int f = tid + i * 256;
                int r = f >> 4, c = (f & 15) * 4;
                rv[i] = *(const float4*)&vbt[(size_t)r * MROWS + k0n + c];
            }
        }

        float sacc[8][4];
#pragma unroll
        for (int nf = 0; nf < 8; nf++)
#pragma unroll
            for (int i = 0; i < 4; i++) sacc[nf][i] = 0.f;

#pragma unroll
        for (int kk = 0; kk < 16; kk++) {
            uint32_t a[4];
            ldm4(a, a_addr(sQb + (uint32_t)wr * (SQ_LD * 4) + kk * 32, SQ_LD * 4));
#pragma unroll
            for (int nfp = 0; nfp < 4; nfp++) {
                uint32_t bfr[4];
                ldm4(bfr, b_addr(sKb + (uint32_t)(nfp * 16) * (SQ_LD * 4) + kk * 32,
                                 SQ_LD * 4));
                mma_tf32(sacc[2 * nfp],     a, bfr);
                mma_tf32(sacc[2 * nfp + 1], a, bfr + 2);
            }
        }

        const int qr0 = q0 + wr + g, qr1 = qr0 + 8;
        const bool need_mask = (k0 + 63 > q0 + wr);
#pragma unroll
        for (int nf = 0; nf < 8; nf++) {
            int key = k0 + nf * 8 + 2 * tg;
#pragma unroll
            for (int i = 0; i < 4; i++) {
                int kc = key + (i & 1);
                int qr = (i < 2) ? qr0 : qr1;
                float s = sacc[nf][i] * scale;
                if (need_mask && kc > qr) s = -1e30f;
                sacc[nf][i] = s;
            }
        }

        float mx0 = -1e30f, mx1 = -1e30f;
#pragma unroll
        for (int nf = 0; nf < 8; nf++) {
            mx0 = fmaxf(mx0, fmaxf(sacc[nf][0], sacc[nf][1]));
            mx1 = fmaxf(mx1, fmaxf(sacc[nf][2], sacc[nf][3]));
        }
        mx0 = fmaxf(mx0, __shfl_xor_sync(0xffffffffu, mx0, 1));
        mx0 = fmaxf(mx0, __shfl_xor_sync(0xffffffffu, mx0, 2));
        mx1 = fmaxf(mx1, __shfl_xor_sync(0xffffffffu, mx1, 1));
        mx1 = fmaxf(mx1, __shfl_xor_sync(0xffffffffu, mx1, 2));

        float mn0 = fmaxf(m0r, mx0), mn1 = fmaxf(m1r, mx1);
        float al0 = __expf(m0r - mn0), al1 = __expf(m1r - mn1);
        float su0 = 0.f, su1 = 0.f;
#pragma unroll
        for (int nf = 0; nf < 8; nf++) {
            float p0 = __expf(sacc[nf][0] - mn0);
            float p1 = __expf(sacc[nf][1] - mn0);
            float p2 = __expf(sacc[nf][2] - mn1);
            float p3 = __expf(sacc[nf][3] - mn1);
            sacc[nf][0] = p0; sacc[nf][1] = p1; sacc[nf][2] = p2; sacc[nf][3] = p3;
            su0 += p0 + p1; su1 += p2 + p3;
        }
        su0 += __shfl_xor_sync(0xffffffffu, su0, 1);
        su0 += __shfl_xor_sync(0xffffffffu, su0, 2);
        su1 += __shfl_xor_sync(0xffffffffu, su1, 1);
        su1 += __shfl_xor_sync(0xffffffffu, su1, 2);
        l0r = l0r * al0 + su0;  l1r = l1r * al1 + su1;
        m0r = mn0;              m1r = mn1;
#pragma unroll
        for (int nf = 0; nf < 16; nf++) {
            oacc[nf][0] *= al0; oacc[nf][1] *= al0;
            oacc[nf][2] *= al1; oacc[nf][3] *= al1;
        }

        const int pr = wr + g;
#pragma unroll
        for (int nf = 0; nf < 8; nf++) {
            int pc = nf * 8 + 2 * tg;
            sP[pr * SP_LD + pc]           = f2tf(sacc[nf][0]);
            sP[pr * SP_LD + pc + 1]       = f2tf(sacc[nf][1]);
            sP[(pr + 8) * SP_LD + pc]     = f2tf(sacc[nf][2]);
            sP[(pr + 8) * SP_LD + pc + 1] = f2tf(sacc[nf][3]);
        }
        __syncwarp();

#pragma unroll
        for (int kf = 0; kf < 8; kf++) {
            uint32_t a[4];
            ldm4(a, a_addr(sPb + (uint32_t)wr * (SP_LD * 4) + kf * 32, SP_LD * 4));
#pragma unroll
            for (int nfp = 0; nfp < 8; nfp++) {
                uint32_t bfr[4];
                ldm4(bfr, b_addr(sVtb + (uint32_t)(nfp * 16) * (SVT_LD * 4) + kf * 32,
                                 SVT_LD * 4));
                mma_tf32(oacc[2 * nfp],     a, bfr);
                mma_tf32(oacc[2 * nfp + 1], a, bfr + 2);
            }
        }
        __syncwarp();
    }

    float il0 = 1.0f / l0r, il1 = 1.0f / l1r;
    const int r0 = q0 + wr + g, r1 = r0 + 8;
#pragma unroll
    for (int nf = 0; nf < 16; nf++) {
        int c = nf * 8 + 2 * tg;
        yb[(size_t)r0 * C_SZ + c]     = oacc[nf][0] * il0;
        yb[(size_t)r0 * C_SZ + c + 1] = oacc[nf][1] * il0;
        yb[(size_t)r1 * C_SZ + c]     = oacc[nf][2] * il1;
        yb[(size_t)r1 * C_SZ + c + 1] = oacc[nf][3] * il1;
    }
}

// ---------------------------------------------------------------------------
// Launch
// ---------------------------------------------------------------------------
extern "C" void kernel_launch(void* const* d_in, const int* in_sizes, int n_in,
                              void* d_out, int out_size) {
    const float* x  = (const float*)d_in[0];
    const float* Wq = (const float*)d_in[1];
    const float* Wk = (const float*)d_in[2];
    const float* Wv = (const float*)d_in[3];
    const float* Wo = (const float*)d_in[4];
    float* out = (float*)d_out;

    float *gq, *gk, *gvt, *gy;
    cudaGetSymbolAddress((void**)&gq, g_q);
    cudaGetSymbolAddress((void**)&gk, g_k);
    cudaGetSymbolAddress((void**)&gvt, g_vt);
    cudaGetSymbolAddress((void**)&gy, g_y);

    cudaFuncSetAttribute(attn_kernel,
                         cudaFuncAttributeMaxDynamicSharedMemorySize,
                         ATTN_SMEM_BYTES);
    cudaFuncSetAttribute(gemm_nt,
                         cudaFuncAttributeMaxDynamicSharedMemorySize,
                         GEMM_SMEM_BYTES);

    init_invf<<<1, 64>>>();
    init_cs<<<T_SZ, 64>>>();

    // Q projection
    gemm_nt<<<dim3(C_SZ / BN, MROWS / BM, 1), 256, GEMM_SMEM_BYTES>>>(
        x, Wq, Wq, gq, gq, C_SZ, C_SZ, 0);
    // K + V projections fused (z=0: K normal; z=1: V transposed epilogue)
    gemm_nt<<<dim3(KVD / BN, MROWS / BM, 2), 256, GEMM_SMEM_BYTES>>>(
        x, Wk, Wv, gk, gvt, KVD, C_SZ, MROWS);

    // RMSNorm + RoPE on q, k
    {
        int total_warps = MROWS * NH + MROWS * NKV;
        int blocks = (total_warps + 7) / 8;
        normrope<<<blocks, 256>>>(gq, gk);
    }

    // Flash attention
    attn_kernel<<<dim3(T_SZ / 128, NH, B_SZ), 256, ATTN_SMEM_BYTES>>>(gq, gk, gvt, gy);

    // Output projection
    gemm_nt<<<dim3(C_SZ / BN, MROWS / BM, 1), 256, GEMM_SMEM_BYTES>>>(
        gy, Wo, Wo, out, out, C_SZ, C_SZ, 0);
}

// round 14
// speedup vs baseline: 1.0343x; 1.0343x over previous
#include <cuda_runtime.h>
#include <cstdint>

// ---------------------------------------------------------------------------
// Problem constants
// ---------------------------------------------------------------------------
#define B_SZ   2
#define T_SZ   2048
#define C_SZ   2048
#define NH     16
#define NKV    4
#define HD     128
#define KVD    (NKV*HD)      // 512
#define MROWS  (B_SZ*T_SZ)   // 4096

// Scratch buffers (allocation-free rule: __device__ globals)
__device__ float g_q[MROWS * C_SZ];
__device__ float g_k[MROWS * KVD];
__device__ float g_vt[KVD * MROWS];    // V transposed (tf32 bits): [kv_dim][b*T]
__device__ float g_y[MROWS * C_SZ];    // attention out (tf32 bits)
__device__ float g_xt[MROWS * C_SZ];   // tf32-rounded x
__device__ float g_wqt[C_SZ * C_SZ];   // tf32-rounded weights
__device__ float g_wkt[KVD * C_SZ];
__device__ float g_wvt[KVD * C_SZ];
__device__ float g_wot[C_SZ * C_SZ];
__device__ float g_invf[64];
__device__ float2 g_cs[T_SZ * 64];     // rope cos/sin table

#define DEV __device__ __forceinline__

DEV uint32_t f2tf(float f) {
    uint32_t u;
    asm("cvt.rna.tf32.f32 %0, %1;" : "=r"(u) : "f"(f));
    return u;
}

DEV void mma_tf32(float* d, const uint32_t* a, const uint32_t* b) {
    asm volatile(
        "mma.sync.aligned.m16n8k8.row.col.f32.tf32.tf32.f32 "
        "{%0,%1,%2,%3}, {%4,%5,%6,%7}, {%8,%9}, {%0,%1,%2,%3};\n"
        : "+f"(d[0]), "+f"(d[1]), "+f"(d[2]), "+f"(d[3])
        : "r"(a[0]), "r"(a[1]), "r"(a[2]), "r"(a[3]),
          "r"(b[0]), "r"(b[1]));
}

DEV uint32_t smem_u32(const void* p) {
    uint32_t a;
    asm("{ .reg .u64 t; cvta.to.shared.u64 t, %1; cvt.u32.u64 %0, t; }"
        : "=r"(a) : "l"(p));
    return a;
}

// ldmatrix x4 (b16 view — pure bit movement)
DEV void ldm4(uint32_t* r, uint32_t addr) {
    asm volatile("ldmatrix.sync.aligned.m8n8.x4.shared.b16 {%0,%1,%2,%3}, [%4];"
                 : "=r"(r[0]), "=r"(r[1]), "=r"(r[2]), "=r"(r[3]) : "r"(addr));
}

// A-fragment tile addressing: 16 rows x 8 f32-cols starting at `tile` (byte addr).
DEV uint32_t a_addr(uint32_t tile, uint32_t ldb) {
    int l = threadIdx.x & 31;
    return tile + (uint32_t)((l & 7) + ((l >> 3) & 1) * 8) * ldb
                + (uint32_t)(l >> 4) * 16;
}
// B-fragment tile addressing (storage [n][k]): 16 n-rows x 8 f32 k-cols.
DEV uint32_t b_addr(uint32_t tile, uint32_t ldb) {
    int l = threadIdx.x & 31;
    return tile + (uint32_t)((l & 7) + (l >> 4) * 8) * ldb
                + (uint32_t)((l >> 3) & 1) * 16;
}

DEV void sts_v4(uint32_t addr, uint32_t x, uint32_t y, uint32_t z, uint32_t w) {
    asm volatile("st.shared.v4.b32 [%0], {%1,%2,%3,%4};"
                 :: "r"(addr), "r"(x), "r"(y), "r"(z), "r"(w) : "memory");
}

DEV void cp16(uint32_t dst, const void* src) {
    asm volatile("cp.async.cg.shared.global [%0], [%1], 16;"
                 :: "r"(dst), "l"(src) : "memory");
}
#define CP_COMMIT() asm volatile("cp.async.commit_group;" ::: "memory")
#define CP_WAIT1()  asm volatile("cp.async.wait_group 1;" ::: "memory")

// ---------------------------------------------------------------------------
// init kernels
// ---------------------------------------------------------------------------
__global__ void init_invf() {
    int i = threadIdx.x;
    if (i < 64) {
        const double LG = 9.210340371976184;   // ln(10000)
        g_invf[i] = (float)exp(-(double)i * (LG / 64.0));
    }
}

__global__ void init_cs() {
    int t = blockIdx.x, i = threadIdx.x;   // 64 threads
    float a = (float)t * g_invf[i];
    g_cs[t * 64 + i] = make_float2(cosf(a), sinf(a));
}

// tf32-round a buffer (vectorized); numerics identical to rounding at use site
__global__ void cvt_tf32(const float* __restrict__ src, float* __restrict__ dst,
                         int n4) {
    int i = blockIdx.x * blockDim.x + threadIdx.x;
    int stride = gridDim.x * blockDim.x;
    for (; i < n4; i += stride) {
        float4 v = ((const float4*)src)[i];
        float4 o;
        o.x = __uint_as_float(f2tf(v.x));
        o.y = __uint_as_float(f2tf(v.y));
        o.z = __uint_as_float(f2tf(v.z));
        o.w = __uint_as_float(f2tf(v.w));
        ((float4*)dst)[i] = o;
    }
}

// ---------------------------------------------------------------------------
// NT GEMM: C[M,N] = A[M,K] * W[N,K]^T  (tf32 mma + ldmatrix fragments)
// Operands are PRE-ROUNDED tf32 bit patterns in gmem -> no cvt in mainloop.
// Block tile 256x128x32, 8 warps 4x2 -> warp tile 64x64.
// cp.async 3-stage pipeline, one __syncthreads per K-tile.
// blockIdx.z selects (W0,C0,normal) vs (W1,C1,transposed tf32-rounded epilogue).
// ---------------------------------------------------------------------------
#define BM 256
#define BN 128
#define BK 32
#define G_LD    (BK + 4)                 // 36 words = 144 B rows
#define A_TILE  (BM * G_LD)
#define B_TILE  (BN * G_LD)
#define STG_W   (A_TILE + B_TILE)        // words per stage (13824)
#define NSTG    3
#define GEMM_SMEM_BYTES (NSTG * STG_W * 4)   // 165888 B

__global__ __launch_bounds__(256, 1)
void gemm_nt(const float* __restrict__ A,
             const float* __restrict__ W0, const float* __restrict__ W1,
             float* __restrict__ C0, float* __restrict__ C1,
             int N, int K, int ldT) {
    extern __shared__ uint32_t smg[];

    const float* W = blockIdx.z ? W1 : W0;
    float* C       = blockIdx.z ? C1 : C0;
    const int transC = blockIdx.z ? 1 : 0;

    const int tid  = threadIdx.x;
    const int warp = tid >> 5, lane = tid & 31;
    const int g = lane >> 2, tg = lane & 3;
    const int wm = (warp >> 1) * 64;
    const int wn = (warp & 1) * 64;
    const int m0 = blockIdx.y * BM, n0 = blockIdx.x * BN;

    const int lr = tid >> 3;                 // 0..31
    const int lc = (tid & 7) * 4;            // 0..28

    const uint32_t sbase = smem_u32(smg);
    const float* Ab = A + (size_t)m0 * K + lc;
    const float* Wb = W + (size_t)n0 * K + lc;

    float acc[4][8][4];
#pragma unroll
    for (int mi = 0; mi < 4; mi++)
#pragma unroll
        for (int nf = 0; nf < 8; nf++)
#pragma unroll
            for (int i = 0; i < 4; i++) acc[mi][nf][i] = 0.f;

    const int niter = K / BK;

    auto issue = [&](int it) {
        const uint32_t sb = sbase + (uint32_t)(it % NSTG) * (STG_W * 4);
        const int koff = it * BK;
#pragma unroll
        for (int i = 0; i < 8; i++) {
            int r = lr + i * 32;
            cp16(sb + (uint32_t)(r * G_LD + lc) * 4, Ab + (size_t)r * K + koff);
        }
#pragma unroll
        for (int i = 0; i < 4; i++) {
            int r = lr + i * 32;
            cp16(sb + (uint32_t)(A_TILE + r * G_LD + lc) * 4, Wb + (size_t)r * K + koff);
        }
    };

    issue(0); CP_COMMIT();
    issue(1); CP_COMMIT();

    for (int it = 0; it < niter; it++) {
        CP_WAIT1();          // this thread's stage `it` complete
        __syncthreads();     // all threads' stage `it` complete

        if (it + 2 < niter) issue(it + 2);
        CP_COMMIT();         // unconditional: keeps wait_group accounting exact

        const uint32_t sb = sbase + (uint32_t)(it % NSTG) * (STG_W * 4);
        const uint32_t sAbyte = sb;
        const uint32_t sBbyte = sb + A_TILE * 4;
#pragma unroll
        for (int kk = 0; kk < 4; kk++) {
            uint32_t av[4][4];
#pragma unroll
            for (int mi = 0; mi < 4; mi++)
                ldm4(av[mi], a_addr(sAbyte + (uint32_t)(wm + 16 * mi) * (G_LD * 4)
                                    + kk * 32, G_LD * 4));
#pragma unroll
            for (int nfp = 0; nfp < 4; nfp++) {
                uint32_t b[4];
                ldm4(b, b_addr(sBbyte + (uint32_t)(wn + 16 * nfp) * (G_LD * 4)
                               + kk * 32, G_LD * 4));
#pragma unroll
                for (int mi = 0; mi < 4; mi++) {
                    mma_tf32(acc[mi][2 * nfp],     av[mi], b);
                    mma_tf32(acc[mi][2 * nfp + 1], av[mi], b + 2);
                }
            }
        }
        __syncthreads();     // all warps done reading stage `it` before reuse
    }

    if (!transC) {
#pragma unroll
        for (int mi = 0; mi < 4; mi++) {
            int r0 = m0 + wm + mi * 16 + g;
#pragma unroll
            for (int nf = 0; nf < 8; nf++) {
                int c0 = n0 + wn + nf * 8 + 2 * tg;
                C[(size_t)r0 * N + c0]           = acc[mi][nf][0];
                C[(size_t)r0 * N + c0 + 1]       = acc[mi][nf][1];
                C[(size_t)(r0 + 8) * N + c0]     = acc[mi][nf][2];
                C[(size_t)(r0 + 8) * N + c0 + 1] = acc[mi][nf][3];
            }
        }
    } else {
        // transposed epilogue (Vt), tf32-rounded at store: Ct[n][m], ldT = MROWS
#pragma unroll
        for (int mi = 0; mi < 4; mi++) {
            int r0 = m0 + wm + mi * 16 + g;
#pragma unroll
            for (int nf = 0; nf < 8; nf++) {
                int c0 = n0 + wn + nf * 8 + 2 * tg;
                C[(size_t)c0 * ldT + r0]           = __uint_as_float(f2tf(acc[mi][nf][0]));
                C[(size_t)(c0 + 1) * ldT + r0]     = __uint_as_float(f2tf(acc[mi][nf][1]));
                C[(size_t)c0 * ldT + r0 + 8]       = __uint_as_float(f2tf(acc[mi][nf][2]));
                C[(size_t)(c0 + 1) * ldT + r0 + 8] = __uint_as_float(f2tf(acc[mi][nf][3]));
            }
        }
    }
}

// ---------------------------------------------------------------------------
// Fused per-head RMSNorm + RoPE for q and k (in place). cos/sin from table.
// Output stored tf32-rounded (rounding previously applied at attention load —
// identical numerics, attention is the only consumer).
// ---------------------------------------------------------------------------
__global__ void normrope(float* __restrict__ q, float* __restrict__ k) {
    int w = (blockIdx.x * blockDim.x + threadIdx.x) >> 5;
    int lane = threadIdx.x & 31;
    const int QW = MROWS * NH;
    float* base;
    int t;
    if (w < QW) {
        int row = w / NH, h = w % NH;
        base = q + (size_t)row * C_SZ + h * HD;
        t = row % T_SZ;
    } else {
        int w2 = w - QW;
        if (w2 >= MROWS * NKV) return;
        int row = w2 / NKV, h = w2 % NKV;
        base = k + (size_t)row * KVD + h * HD;
        t = row % T_SZ;
    }
    float x0 = base[lane], x1 = base[lane + 32], x2 = base[lane + 64], x3 = base[lane + 96];
    float ss = x0 * x0 + x1 * x1 + x2 * x2 + x3 * x3;
#pragma unroll
    for (int o = 16; o; o >>= 1) ss += __shfl_xor_sync(0xffffffffu, ss, o);
    float rn = rsqrtf(ss * (1.0f / 128.0f) + 1.1920928955078125e-7f);
    x0 *= rn; x1 *= rn; x2 *= rn; x3 *= rn;

    float2 cs0 = g_cs[t * 64 + lane];
    float2 cs1 = g_cs[t * 64 + lane + 32];
    float c0 = cs0.x, s0 = cs0.y;
    float c1 = cs1.x, s1 = cs1.y;

    base[lane]      = __uint_as_float(f2tf( x0 * c0 + x2 * s0));
    base[lane + 64] = __uint_as_float(f2tf(-x0 * s0 + x2 * c0));
    base[lane + 32] = __uint_as_float(f2tf( x1 * c1 + x3 * s1));
    base[lane + 96] = __uint_as_float(f2tf(-x1 * s1 + x3 * c1));
}

// ---------------------------------------------------------------------------
// Flash attention, causal, GQA (group=4). Br=128, Bc=64, D=128.
// 8 warps; warp w owns rows [16w,16w+16). tf32 mma + ldmatrix fragments.
// Inputs pre-rounded tf32 bits -> staging is pure byte movement (no cvt).
// Epilogue writes y tf32-rounded (Wo consumed it rounded before — identical).
// ---------------------------------------------------------------------------
#define SQ_LD 132
#define SVT_LD 68
#define SP_LD 68
#define OFF_Q 0
#define OFF_K (128 * SQ_LD)
#define OFF_VT (OFF_K + 64 * SQ_LD)
#define OFF_P (OFF_VT + 128 * SVT_LD)
#define ATTN_SMEM_WORDS (OFF_P + 128 * SP_LD)
#define ATTN_SMEM_BYTES (ATTN_SMEM_WORDS * 4)

__global__ __launch_bounds__(256, 1)
void attn_kernel(const float* __restrict__ q, const float* __restrict__ k,
                 const float* __restrict__ vt, float* __restrict__ y) {
    extern __shared__ uint32_t sm[];
    uint32_t* sQ  = sm + OFF_Q;
    uint32_t* sP  = sm + OFF_P;

    const int tid = threadIdx.x, warp = tid >> 5, lane = tid & 31;
    const int g = lane >> 2, tg = lane & 3;
    const int q0 = (int)(gridDim.x - 1 - blockIdx.x) * 128;
    const int h = blockIdx.y, b = blockIdx.z;
    const int kvh = h >> 2;

    const float* qb = q + (size_t)b * T_SZ * C_SZ + (size_t)h * HD;
    const float* kb = k + (size_t)b * T_SZ * KVD + (size_t)kvh * HD;
    const float* vbt = vt + (size_t)(kvh * HD) * MROWS + (size_t)b * T_SZ;
    float*       yb = y + (size_t)b * T_SZ * C_SZ + (size_t)h * HD;

    const uint32_t sQb  = smem_u32(sm + OFF_Q);
    const uint32_t sKb  = smem_u32(sm + OFF_K);
    const uint32_t sVtb = smem_u32(sm + OFF_VT);
    const uint32_t sPb  = smem_u32(sm + OFF_P);

    float4 rk[8], rv[8];
#pragma unroll
    for (int i = 0; i < 8; i++) {
        int f = tid + i * 256;
        int r = f >> 5, c = (f & 31) * 4;
        rk[i] = *(const float4*)&kb[(size_t)r * KVD + c];
    }
#pragma unroll
    for (int i = 0; i < 8; i++) {
        int f = tid + i * 256;
        int r = f >> 4, c = (f & 15) * 4;
        rv[i] = *(const float4*)&vbt[(size_t)r * MROWS + c];
    }

#pragma unroll
    for (int i = 0; i < 16; i++) {
        int f = tid + i * 256;
        int r = f >> 5, c = (f & 31) * 4;
        float4 v4 = *(const float4*)&qb[(size_t)(q0 + r) * C_SZ + c];
        uint32_t* d = &sQ[r * SQ_LD + c];
        d[0] = __float_as_uint(v4.x); d[1] = __float_as_uint(v4.y);
        d[2] = __float_as_uint(v4.z); d[3] = __float_as_uint(v4.w);
    }

    float oacc[16][4];
#pragma unroll
    for (int nf = 0; nf < 16; nf++)
#pragma unroll
        for (int i = 0; i < 4; i++) oacc[nf][i] = 0.f;
    float m0r = -1e30f, m1r = -1e30f, l0r = 0.f, l1r = 0.f;

    const int wr = warp * 16;
    const int ntiles = q0 / 64 + 2;
    const float scale = 0.08838834764831845f;

    for (int j = 0; j < ntiles; j++) {
        const int k0 = j * 64;
        __syncthreads();

#pragma unroll
        for (int i = 0; i < 8; i++) {
            int f = tid + i * 256;
            int r = f >> 5, c = (f & 31) * 4;
            sts_v4(sKb + (uint32_t)(r * SQ_LD + c) * 4,
                   __float_as_uint(rk[i].x), __float_as_uint(rk[i].y),
                   __float_as_uint(rk[i].z), __float_as_uint(rk[i].w));
        }
#pragma unroll
        for (int i = 0; i < 8; i++) {
            int f = tid + i * 256;
            int r = f >> 4, c = (f & 15) * 4;
            sts_v4(sVtb + (uint32_t)(r * SVT_LD + c) * 4,
                   __float_as_uint(rv[i].x), __float_as_uint(rv[i].y),
                   __float_as_uint(rv[i].z), __float_as_uint(rv[i].w));
        }
        __syncthreads();

        if (j + 1 < ntiles) {
            const int k0n = k0 + 64;
#pragma unroll
            for (int i = 0; i < 8; i++) {
                int f = tid + i * 256;
                int r = f >> 5, c = (f & 31) * 4;
                rk[i] = *(const float4*)&kb[(size_t)(k0n + r) * KVD + c];
            }
#pragma unroll
            for (int i = 0; i < 8; i++) {
                int f = tid + i * 256;
                int r = f >> 4, c = (f & 15) * 4;
                rv[i] = *(const float4*)&vbt[(size_t)r * MROWS + k0n + c];
            }
        }

        float sacc[8][4];
#pragma unroll
        for (int nf = 0; nf < 8; nf++)
#pragma unroll
            for (int i = 0; i < 4; i++) sacc[nf][i] = 0.f;

#pragma unroll
        for (int kk = 0; kk < 16; kk++) {
            uint32_t a[4];
            ldm4(a, a_addr(sQb + (uint32_t)wr * (SQ_LD * 4) + kk * 32, SQ_LD * 4));
#pragma unroll
            for (int nfp = 0; nfp < 4; nfp++) {
                uint32_t bfr[4];
                ldm4(bfr, b_addr(sKb + (uint32_t)(nfp * 16) * (SQ_LD * 4) + kk * 32,
                                 SQ_LD * 4));
                mma_tf32(sacc[2 * nfp],     a, bfr);
                mma_tf32(sacc[2 * nfp + 1], a, bfr + 2);
            }
        }

        const int qr0 = q0 + wr + g, qr1 = qr0 + 8;
        const bool need_mask = (k0 + 63 > q0 + wr);
#pragma unroll
        for (int nf = 0; nf < 8; nf++) {
            int key = k0 + nf * 8 + 2 * tg;
#pragma unroll
            for (int i = 0; i < 4; i++) {
                int kc = key + (i & 1);
                int qr = (i < 2) ? qr0 : qr1;
                float s = sacc[nf][i] * scale;
                if (need_mask && kc > qr) s = -1e30f;
                sacc[nf][i] = s;
            }
        }

        float mx0 = -1e30f, mx1 = -1e30f;
#pragma unroll
        for (int nf = 0; nf < 8; nf++) {
            mx0 = fmaxf(mx0, fmaxf(sacc[nf][0], sacc[nf][1]));
            mx1 = fmaxf(mx1, fmaxf(sacc[nf][2], sacc[nf][3]));
        }
        mx0 = fmaxf(mx0, __shfl_xor_sync(0xffffffffu, mx0, 1));
        mx0 = fmaxf(mx0, __shfl_xor_sync(0xffffffffu, mx0, 2));
        mx1 = fmaxf(mx1, __shfl_xor_sync(0xffffffffu, mx1, 1));
        mx1 = fmaxf(mx1, __shfl_xor_sync(0xffffffffu, mx1, 2));

        float mn0 = fmaxf(m0r, mx0), mn1 = fmaxf(m1r, mx1);
        float al0 = __expf(m0r - mn0), al1 = __expf(m1r - mn1);
        float su0 = 0.f, su1 = 0.f;
#pragma unroll
        for (int nf = 0; nf < 8; nf++) {
            float p0 = __expf(sacc[nf][0] - mn0);
            float p1 = __expf(sacc[nf][1] - mn0);
            float p2 = __expf(sacc[nf][2] - mn1);
            float p3 = __expf(sacc[nf][3] - mn1);
            sacc[nf][0] = p0; sacc[nf][1] = p1; sacc[nf][2] = p2; sacc[nf][3] = p3;
            su0 += p0 + p1; su1 += p2 + p3;
        }
        su0 += __shfl_xor_sync(0xffffffffu, su0, 1);
        su0 += __shfl_xor_sync(0xffffffffu, su0, 2);
        su1 += __shfl_xor_sync(0xffffffffu, su1, 1);
        su1 += __shfl_xor_sync(0xffffffffu, su1, 2);
        l0r = l0r * al0 + su0;  l1r = l1r * al1 + su1;
        m0r = mn0;              m1r = mn1;
#pragma unroll
        for (int nf = 0; nf < 16; nf++) {
            oacc[nf][0] *= al0; oacc[nf][1] *= al0;
            oacc[nf][2] *= al1; oacc[nf][3] *= al1;
        }

        const int pr = wr + g;
#pragma unroll
        for (int nf = 0; nf < 8; nf++) {
            int pc = nf * 8 + 2 * tg;
            sP[pr * SP_LD + pc]           = f2tf(sacc[nf][0]);
            sP[pr * SP_LD + pc + 1]       = f2tf(sacc[nf][1]);
            sP[(pr + 8) * SP_LD + pc]     = f2tf(sacc[nf][2]);
            sP[(pr + 8) * SP_LD + pc + 1] = f2tf(sacc[nf][3]);
        }
        __syncwarp();

#pragma unroll
        for (int kf = 0; kf < 8; kf++) {
            uint32_t a[4];
            ldm4(a, a_addr(sPb + (uint32_t)wr * (SP_LD * 4) + kf * 32, SP_LD * 4));
#pragma unroll
            for (int nfp = 0; nfp < 8; nfp++) {
                uint32_t bfr[4];
                ldm4(bfr, b_addr(sVtb + (uint32_t)(nfp * 16) * (SVT_LD * 4) + kf * 32,
                                 SVT_LD * 4));
                mma_tf32(oacc[2 * nfp],     a, bfr);
                mma_tf32(oacc[2 * nfp + 1], a, bfr + 2);
            }
        }
        __syncwarp();
    }

    // epilogue: y stored tf32-rounded (Wo's load-side rounding moved here)
    float il0 = 1.0f / l0r, il1 = 1.0f / l1r;
    const int r0 = q0 + wr + g, r1 = r0 + 8;
#pragma unroll
    for (int nf = 0; nf < 16; nf++) {
        int c = nf * 8 + 2 * tg;
        yb[(size_t)r0 * C_SZ + c]     = __uint_as_float(f2tf(oacc[nf][0] * il0));
        yb[(size_t)r0 * C_SZ + c + 1] = __uint_as_float(f2tf(oacc[nf][1] * il0));
        yb[(size_t)r1 * C_SZ + c]     = __uint_as_float(f2tf(oacc[nf][2] * il1));
        yb[(size_t)r1 * C_SZ + c + 1] = __uint_as_float(f2tf(oacc[nf][3] * il1));
    }
}

// ---------------------------------------------------------------------------
// Launch
// ---------------------------------------------------------------------------
extern "C" void kernel_launch(void* const* d_in, const int* in_sizes, int n_in,
                              void* d_out, int out_size) {
    const float* x  = (const float*)d_in[0];
    const float* Wq = (const float*)d_in[1];
    const float* Wk = (const float*)d_in[2];
    const float* Wv = (const float*)d_in[3];
    const float* Wo = (const float*)d_in[4];
    float* out = (float*)d_out;

    float *gq, *gk, *gvt, *gy, *gxt, *gwqt, *gwkt, *gwvt, *gwot;
    cudaGetSymbolAddress((void**)&gq, g_q);
    cudaGetSymbolAddress((void**)&gk, g_k);
    cudaGetSymbolAddress((void**)&gvt, g_vt);
    cudaGetSymbolAddress((void**)&gy, g_y);
    cudaGetSymbolAddress((void**)&gxt, g_xt);
    cudaGetSymbolAddress((void**)&gwqt, g_wqt);
    cudaGetSymbolAddress((void**)&gwkt, g_wkt);
    cudaGetSymbolAddress((void**)&gwvt, g_wvt);
    cudaGetSymbolAddress((void**)&gwot, g_wot);

    cudaFuncSetAttribute(attn_kernel,
                         cudaFuncAttributeMaxDynamicSharedMemorySize,
                         ATTN_SMEM_BYTES);
    cudaFuncSetAttribute(gemm_nt,
                         cudaFuncAttributeMaxDynamicSharedMemorySize,
                         GEMM_SMEM_BYTES);

    init_invf<<<1, 64>>>();
    init_cs<<<T_SZ, 64>>>();

    // Pre-round operands to tf32 (one-time; numerics identical to per-use cvt)
    cvt_tf32<<<1024, 256>>>(x,  gxt,  MROWS * C_SZ / 4);
    cvt_tf32<<<1024, 256>>>(Wq, gwqt, C_SZ * C_SZ / 4);
    cvt_tf32<<<256,  256>>>(Wk, gwkt, KVD * C_SZ / 4);
    cvt_tf32<<<256,  256>>>(Wv, gwvt, KVD * C_SZ / 4);
    cvt_tf32<<<1024, 256>>>(Wo, gwot, C_SZ * C_SZ / 4);

    // Q projection
    gemm_nt<<<dim3(C_SZ / BN, MROWS / BM, 1), 256, GEMM_SMEM_BYTES>>>(
        gxt, gwqt, gwqt, gq, gq, C_SZ, C_SZ, 0);
    // K + V projections fused (z=0: K normal; z=1: V transposed tf32 epilogue)
    gemm_nt<<<dim3(KVD / BN, MROWS / BM, 2), 256, GEMM_SMEM_BYTES>>>(
        gxt, gwkt, gwvt, gk, gvt, KVD, C_SZ, MROWS);

    // RMSNorm + RoPE on q, k (writes tf32-rounded)
    {
        int total_warps = MROWS * NH + MROWS * NKV;
        int blocks = (total_warps + 7) / 8;
        normrope<<<blocks, 256>>>(gq, gk);
    }

    // Flash attention
    attn_kernel<<<dim3(T_SZ / 128, NH, B_SZ), 256, ATTN_SMEM_BYTES>>>(gq, gk, gvt, gy);

    // Output projection (gy already tf32-rounded)
    gemm_nt<<<dim3(C_SZ / BN, MROWS / BM, 1), 256, GEMM_SMEM_BYTES>>>(
        gy, gwot, gwot, out, out, C_SZ, C_SZ, 0);
}

// round 17
// speedup vs baseline: 1.0391x; 1.0047x over previous
#include <cuda_runtime.h>
#include <cstdint>

// ---------------------------------------------------------------------------
// Problem constants
// ---------------------------------------------------------------------------
#define B_SZ   2
#define T_SZ   2048
#define C_SZ   2048
#define NH     16
#define NKV    4
#define HD     128
#define KVD    (NKV*HD)      // 512
#define MROWS  (B_SZ*T_SZ)   // 4096

// Scratch buffers (allocation-free rule: __device__ globals)
__device__ float g_q[MROWS * C_SZ];
__device__ float g_k[MROWS * KVD];
__device__ float g_vt[KVD * MROWS];    // V transposed (tf32 bits): [kv_dim][b*T]
__device__ float g_y[MROWS * C_SZ];    // attention out (tf32 bits)
__device__ float g_xt[MROWS * C_SZ];   // tf32-rounded x
__device__ float g_wqt[C_SZ * C_SZ];   // tf32-rounded weights
__device__ float g_wkt[KVD * C_SZ];
__device__ float g_wvt[KVD * C_SZ];
__device__ float g_wot[C_SZ * C_SZ];
__device__ float g_invf[64];
__device__ float2 g_cs[T_SZ * 64];     // rope cos/sin table

#define DEV __device__ __forceinline__

DEV uint32_t f2tf(float f) {
    uint32_t u;
    asm("cvt.rna.tf32.f32 %0, %1;" : "=r"(u) : "f"(f));
    return u;
}

DEV void mma_tf32(float* d, const uint32_t* a, const uint32_t* b) {
    asm volatile(
        "mma.sync.aligned.m16n8k8.row.col.f32.tf32.tf32.f32 "
        "{%0,%1,%2,%3}, {%4,%5,%6,%7}, {%8,%9}, {%0,%1,%2,%3};\n"
        : "+f"(d[0]), "+f"(d[1]), "+f"(d[2]), "+f"(d[3])
        : "r"(a[0]), "r"(a[1]), "r"(a[2]), "r"(a[3]),
          "r"(b[0]), "r"(b[1]));
}

DEV uint32_t smem_u32(const void* p) {
    uint32_t a;
    asm("{ .reg .u64 t; cvta.to.shared.u64 t, %1; cvt.u32.u64 %0, t; }"
        : "=r"(a) : "l"(p));
    return a;
}

// ldmatrix x4 (b16 view — pure bit movement)
DEV void ldm4(uint32_t* r, uint32_t addr) {
    asm volatile("ldmatrix.sync.aligned.m8n8.x4.shared.b16 {%0,%1,%2,%3}, [%4];"
                 : "=r"(r[0]), "=r"(r[1]), "=r"(r[2]), "=r"(r[3]) : "r"(addr));
}

// A-fragment tile addressing: 16 rows x 8 f32-cols starting at `tile` (byte addr).
DEV uint32_t a_addr(uint32_t tile, uint32_t ldb) {
    int l = threadIdx.x & 31;
    return tile + (uint32_t)((l & 7) + ((l >> 3) & 1) * 8) * ldb
                + (uint32_t)(l >> 4) * 16;
}
// B-fragment tile addressing (storage [n][k]): 16 n-rows x 8 f32 k-cols.
DEV uint32_t b_addr(uint32_t tile, uint32_t ldb) {
    int l = threadIdx.x & 31;
    return tile + (uint32_t)((l & 7) + (l >> 4) * 8) * ldb
                + (uint32_t)((l >> 3) & 1) * 16;
}

DEV void sts_v4(uint32_t addr, uint32_t x, uint32_t y, uint32_t z, uint32_t w) {
    asm volatile("st.shared.v4.b32 [%0], {%1,%2,%3,%4};"
                 :: "r"(addr), "r"(x), "r"(y), "r"(z), "r"(w) : "memory");
}

DEV void cp16(uint32_t dst, const void* src) {
    asm volatile("cp.async.cg.shared.global [%0], [%1], 16;"
                 :: "r"(dst), "l"(src) : "memory");
}
#define CP_COMMIT() asm volatile("cp.async.commit_group;" ::: "memory")
#define CP_WAIT2()  asm volatile("cp.async.wait_group 2;" ::: "memory")

// ---------------------------------------------------------------------------
// init kernels
// ---------------------------------------------------------------------------
__global__ void init_invf() {
    int i = threadIdx.x;
    if (i < 64) {
        const double LG = 9.210340371976184;   // ln(10000)
        g_invf[i] = (float)exp(-(double)i * (LG / 64.0));
    }
}

__global__ void init_cs() {
    int t = blockIdx.x, i = threadIdx.x;   // 64 threads
    float a = (float)t * g_invf[i];
    g_cs[t * 64 + i] = make_float2(cosf(a), sinf(a));
}

// tf32-round a buffer (vectorized); numerics identical to rounding at use site
__global__ void cvt_tf32(const float* __restrict__ src, float* __restrict__ dst,
                         int n4) {
    int i = blockIdx.x * blockDim.x + threadIdx.x;
    int stride = gridDim.x * blockDim.x;
    for (; i < n4; i += stride) {
        float4 v = ((const float4*)src)[i];
        float4 o;
        o.x = __uint_as_float(f2tf(v.x));
        o.y = __uint_as_float(f2tf(v.y));
        o.z = __uint_as_float(f2tf(v.z));
        o.w = __uint_as_float(f2tf(v.w));
        ((float4*)dst)[i] = o;
    }
}

// ---------------------------------------------------------------------------
// NT GEMM: C[M,N] = A[M,K] * W[N,K]^T  (tf32 mma + ldmatrix fragments)
// Operands are PRE-ROUNDED tf32 bit patterns in gmem -> no cvt in mainloop.
// Block tile 256x128x32, 8 warps 4x2 -> warp tile 64x64.
// cp.async 4-stage pipeline, ONE __syncthreads per K-tile:
//   issue(it+3) writes buf (it+3)%4 == (it-1)%4, whose readers all passed
//   this iteration's barrier (compute(it-1) precedes it in program order).
// blockIdx.z selects (W0,C0,normal) vs (W1,C1,transposed tf32-rounded epilogue).
// ---------------------------------------------------------------------------
#define BM 256
#define BN 128
#define BK 32
#define G_LD    (BK + 4)                 // 36 words = 144 B rows
#define A_TILE  (BM * G_LD)
#define B_TILE  (BN * G_LD)
#define STG_W   (A_TILE + B_TILE)        // words per stage (13824)
#define NSTG    4
#define GEMM_SMEM_BYTES (NSTG * STG_W * 4)   // 221184 B

__global__ __launch_bounds__(256, 1)
void gemm_nt(const float* __restrict__ A,
             const float* __restrict__ W0, const float* __restrict__ W1,
             float* __restrict__ C0, float* __restrict__ C1,
             int N, int K, int ldT) {
    extern __shared__ uint32_t smg[];

    const float* W = blockIdx.z ? W1 : W0;
    float* C       = blockIdx.z ? C1 : C0;
    const int transC = blockIdx.z ? 1 : 0;

    const int tid  = threadIdx.x;
    const int warp = tid >> 5, lane = tid & 31;
    const int g = lane >> 2, tg = lane & 3;
    const int wm = (warp >> 1) * 64;
    const int wn = (warp & 1) * 64;
    const int m0 = blockIdx.y * BM, n0 = blockIdx.x * BN;

    const int lr = tid >> 3;                 // 0..31
    const int lc = (tid & 7) * 4;            // 0..28

    const uint32_t sbase = smem_u32(smg);
    const float* Ab = A + (size_t)m0 * K + lc;
    const float* Wb = W + (size_t)n0 * K + lc;

    float acc[4][8][4];
#pragma unroll
    for (int mi = 0; mi < 4; mi++)
#pragma unroll
        for (int nf = 0; nf < 8; nf++)
#pragma unroll
            for (int i = 0; i < 4; i++) acc[mi][nf][i] = 0.f;

    const int niter = K / BK;

    auto issue = [&](int it) {
        const uint32_t sb = sbase + (uint32_t)(it % NSTG) * (STG_W * 4);
        const int koff = it * BK;
#pragma unroll
        for (int i = 0; i < 8; i++) {
            int r = lr + i * 32;
            cp16(sb + (uint32_t)(r * G_LD + lc) * 4, Ab + (size_t)r * K + koff);
        }
#pragma unroll
        for (int i = 0; i < 4; i++) {
            int r = lr + i * 32;
            cp16(sb + (uint32_t)(A_TILE + r * G_LD + lc) * 4, Wb + (size_t)r * K + koff);
        }
    };

    // prologue: stages 0,1,2 in flight
    issue(0); CP_COMMIT();
    issue(1); CP_COMMIT();
    issue(2); CP_COMMIT();

    for (int it = 0; it < niter; it++) {
        CP_WAIT2();          // <=2 groups outstanding -> stage `it` complete
        __syncthreads();     // all threads see stage `it`; compute(it-1) done

        if (it + 3 < niter) issue(it + 3);
        CP_COMMIT();         // unconditional: keeps wait_group accounting exact

        const uint32_t sb = sbase + (uint32_t)(it % NSTG) * (STG_W * 4);
        const uint32_t sAbyte = sb;
        const uint32_t sBbyte = sb + A_TILE * 4;
#pragma unroll
        for (int kk = 0; kk < 4; kk++) {
            uint32_t av[4][4];
#pragma unroll
            for (int mi = 0; mi < 4; mi++)
                ldm4(av[mi], a_addr(sAbyte + (uint32_t)(wm + 16 * mi) * (G_LD * 4)
                                    + kk * 32, G_LD * 4));
#pragma unroll
            for (int nfp = 0; nfp < 4; nfp++) {
                uint32_t b[4];
                ldm4(b, b_addr(sBbyte + (uint32_t)(wn + 16 * nfp) * (G_LD * 4)
                               + kk * 32, G_LD * 4));
#pragma unroll
                for (int mi = 0; mi < 4; mi++) {
                    mma_tf32(acc[mi][2 * nfp],     av[mi], b);
                    mma_tf32(acc[mi][2 * nfp + 1], av[mi], b + 2);
                }
            }
        }
        // no trailing sync: next iteration's barrier protects buffer reuse
    }

    if (!transC) {
#pragma unroll
        for (int mi = 0; mi < 4; mi++) {
            int r0 = m0 + wm + mi * 16 + g;
#pragma unroll
            for (int nf = 0; nf < 8; nf++) {
                int c0 = n0 + wn + nf * 8 + 2 * tg;
                C[(size_t)r0 * N + c0]           = acc[mi][nf][0];
                C[(size_t)r0 * N + c0 + 1]       = acc[mi][nf][1];
                C[(size_t)(r0 + 8) * N + c0]     = acc[mi][nf][2];
                C[(size_t)(r0 + 8) * N + c0 + 1] = acc[mi][nf][3];
            }
        }
    } else {
        // transposed epilogue (Vt), tf32-rounded at store: Ct[n][m], ldT = MROWS
#pragma unroll
        for (int mi = 0; mi < 4; mi++) {
            int r0 = m0 + wm + mi * 16 + g;
#pragma unroll
            for (int nf = 0; nf < 8; nf++) {
                int c0 = n0 + wn + nf * 8 + 2 * tg;
                C[(size_t)c0 * ldT + r0]           = __uint_as_float(f2tf(acc[mi][nf][0]));
                C[(size_t)(c0 + 1) * ldT + r0]     = __uint_as_float(f2tf(acc[mi][nf][1]));
                C[(size_t)c0 * ldT + r0 + 8]       = __uint_as_float(f2tf(acc[mi][nf][2]));
                C[(size_t)(c0 + 1) * ldT + r0 + 8] = __uint_as_float(f2tf(acc[mi][nf][3]));
            }
        }
    }
}

// ---------------------------------------------------------------------------
// Fused per-head RMSNorm + RoPE for q and k (in place). cos/sin from table.
// Output stored tf32-rounded (identical numerics; attention is sole consumer).
// ---------------------------------------------------------------------------
__global__ void normrope(float* __restrict__ q, float* __restrict__ k) {
    int w = (blockIdx.x * blockDim.x + threadIdx.x) >> 5;
    int lane = threadIdx.x & 31;
    const int QW = MROWS * NH;
    float* base;
    int t;
    if (w < QW) {
        int row = w / NH, h = w % NH;
        base = q + (size_t)row * C_SZ + h * HD;
        t = row % T_SZ;
    } else {
        int w2 = w - QW;
        if (w2 >= MROWS * NKV) return;
        int row = w2 / NKV, h = w2 % NKV;
        base = k + (size_t)row * KVD + h * HD;
        t = row % T_SZ;
    }
    float x0 = base[lane], x1 = base[lane + 32], x2 = base[lane + 64], x3 = base[lane + 96];
    float ss = x0 * x0 + x1 * x1 + x2 * x2 + x3 * x3;
#pragma unroll
    for (int o = 16; o; o >>= 1) ss += __shfl_xor_sync(0xffffffffu, ss, o);
    float rn = rsqrtf(ss * (1.0f / 128.0f) + 1.1920928955078125e-7f);
    x0 *= rn; x1 *= rn; x2 *= rn; x3 *= rn;

    float2 cs0 = g_cs[t * 64 + lane];
    float2 cs1 = g_cs[t * 64 + lane + 32];
    float c0 = cs0.x, s0 = cs0.y;
    float c1 = cs1.x, s1 = cs1.y;

    base[lane]      = __uint_as_float(f2tf( x0 * c0 + x2 * s0));
    base[lane + 64] = __uint_as_float(f2tf(-x0 * s0 + x2 * c0));
    base[lane + 32] = __uint_as_float(f2tf( x1 * c1 + x3 * s1));
    base[lane + 96] = __uint_as_float(f2tf(-x1 * s1 + x3 * c1));
}

// ---------------------------------------------------------------------------
// Flash attention, causal, GQA (group=4). Br=128, Bc=64, D=128.
// 8 warps; warp w owns rows [16w,16w+16). tf32 mma + ldmatrix fragments.
// Inputs pre-rounded tf32 bits -> staging is pure byte movement (no cvt).
// Epilogue writes y tf32-rounded.
// ---------------------------------------------------------------------------
#define SQ_LD 132
#define SVT_LD 68
#define SP_LD 68
#define OFF_Q 0
#define OFF_K (128 * SQ_LD)
#define OFF_VT (OFF_K + 64 * SQ_LD)
#define OFF_P (OFF_VT + 128 * SVT_LD)
#define ATTN_SMEM_WORDS (OFF_P + 128 * SP_LD)
#define ATTN_SMEM_BYTES (ATTN_SMEM_WORDS * 4)

__global__ __launch_bounds__(256, 1)
void attn_kernel(const float* __restrict__ q, const float* __restrict__ k,
                 const float* __restrict__ vt, float* __restrict__ y) {
    extern __shared__ uint32_t sm[];
    uint32_t* sQ  = sm + OFF_Q;
    uint32_t* sP  = sm + OFF_P;

    const int tid = threadIdx.x, warp = tid >> 5, lane = tid & 31;
    const int g = lane >> 2, tg = lane & 3;
    const int q0 = (int)(gridDim.x - 1 - blockIdx.x) * 128;
    const int h = blockIdx.y, b = blockIdx.z;
    const int kvh = h >> 2;

    const float* qb = q + (size_t)b * T_SZ * C_SZ + (size_t)h * HD;
    const float* kb = k + (size_t)b * T_SZ * KVD + (size_t)kvh * HD;
    const float* vbt = vt + (size_t)(kvh * HD) * MROWS + (size_t)b * T_SZ;
    float*       yb = y + (size_t)b * T_SZ * C_SZ + (size_t)h * HD;

    const uint32_t sQb  = smem_u32(sm + OFF_Q);
    const uint32_t sKb  = smem_u32(sm + OFF_K);
    const uint32_t sVtb = smem_u32(sm + OFF_VT);
    const uint32_t sPb  = smem_u32(sm + OFF_P);

    float4 rk[8], rv[8];
#pragma unroll
    for (int i = 0; i < 8; i++) {
        int f = tid + i * 256;
        int r = f >> 5, c = (f & 31) * 4;
        rk[i] = *(const float4*)&kb[(size_t)r * KVD + c];
    }
#pragma unroll
    for (int i = 0; i < 8; i++) {
        int f = tid + i * 256;
        int r = f >> 4, c = (f & 15) * 4;
        rv[i] = *(const float4*)&vbt[(size_t)r * MROWS + c];
    }

#pragma unroll
    for (int i = 0; i < 16; i++) {
        int f = tid + i * 256;
        int r = f >> 5, c = (f & 31) * 4;
        float4 v4 = *(const float4*)&qb[(size_t)(q0 + r) * C_SZ + c];
        uint32_t* d = &sQ[r * SQ_LD + c];
        d[0] = __float_as_uint(v4.x); d[1] = __float_as_uint(v4.y);
        d[2] = __float_as_uint(v4.z); d[3] = __float_as_uint(v4.w);
    }

    float oacc[16][4];
#pragma unroll
    for (int nf = 0; nf < 16; nf++)
#pragma unroll
        for (int i = 0; i < 4; i++) oacc[nf][i] = 0.f;
    float m0r = -1e30f, m1r = -1e30f, l0r = 0.f, l1r = 0.f;

    const int wr = warp * 16;
    const int ntiles = q0 / 64 + 2;
    const float scale = 0.08838834764831845f;

    for (int j = 0; j < ntiles; j++) {
        const int k0 = j * 64;
        __syncthreads();

#pragma unroll
        for (int i = 0; i < 8; i++) {
            int f = tid + i * 256;
            int r = f >> 5, c = (f & 31) * 4;
            sts_v4(sKb + (uint32_t)(r * SQ_LD + c) * 4,
                   __float_as_uint(rk[i].x), __float_as_uint(rk[i].y),
                   __float_as_uint(rk[i].z), __float_as_uint(rk[i].w));
        }
#pragma unroll
        for (int i = 0; i < 8; i++) {
            int f = tid + i * 256;
            int r = f >> 4, c = (f & 15) * 4;
            sts_v4(sVtb + (uint32_t)(r * SVT_LD + c) * 4,
                   __float_as_uint(rv[i].x), __float_as_uint(rv[i].y),
                   __float_as_uint(rv[i].z), __float_as_uint(rv[i].w));
        }
        __syncthreads();

        if (j + 1 < ntiles) {
            const int k0n = k0 + 64;
#pragma unroll
            for (int i = 0; i < 8; i++) {
                int f = tid + i * 256;
                int r = f >> 5, c = (f & 31) * 4;
                rk[i] = *(const float4*)&kb[(size_t)(k0n + r) * KVD + c];
            }
#pragma unroll
            for (int i = 0; i < 8; i++) {
                int f = tid + i * 256;
                int r = f >> 4, c = (f & 15) * 4;
                rv[i] = *(const float4*)&vbt[(size_t)r * MROWS + k0n + c];
            }
        }

        float sacc[8][4];
#pragma unroll
        for (int nf = 0; nf < 8; nf++)
#pragma unroll
            for (int i = 0; i < 4; i++) sacc[nf][i] = 0.f;

#pragma unroll
        for (int kk = 0; kk < 16; kk++) {
            uint32_t a[4];
            ldm4(a, a_addr(sQb + (uint32_t)wr * (SQ_LD * 4) + kk * 32, SQ_LD * 4));
#pragma unroll
            for (int nfp = 0; nfp < 4; nfp++) {
                uint32_t bfr[4];
                ldm4(bfr, b_addr(sKb + (uint32_t)(nfp * 16) * (SQ_LD * 4) + kk * 32,
                                 SQ_LD * 4));
                mma_tf32(sacc[2 * nfp],     a, bfr);
                mma_tf32(sacc[2 * nfp + 1], a, bfr + 2);
            }
        }

        const int qr0 = q0 + wr + g, qr1 = qr0 + 8;
        const bool need_mask = (k0 + 63 > q0 + wr);
#pragma unroll
        for (int nf = 0; nf < 8; nf++) {
            int key = k0 + nf * 8 + 2 * tg;
#pragma unroll
            for (int i = 0; i < 4; i++) {
                int kc = key + (i & 1);
                int qr = (i < 2) ? qr0 : qr1;
                float s = sacc[nf][i] * scale;
                if (need_mask && kc > qr) s = -1e30f;
                sacc[nf][i] = s;
            }
        }

        float mx0 = -1e30f, mx1 = -1e30f;
#pragma unroll
        for (int nf = 0; nf < 8; nf++) {
            mx0 = fmaxf(mx0, fmaxf(sacc[nf][0], sacc[nf][1]));
            mx1 = fmaxf(mx1, fmaxf(sacc[nf][2], sacc[nf][3]));
        }
        mx0 = fmaxf(mx0, __shfl_xor_sync(0xffffffffu, mx0, 1));
        mx0 = fmaxf(mx0, __shfl_xor_sync(0xffffffffu, mx0, 2));
        mx1 = fmaxf(mx1, __shfl_xor_sync(0xffffffffu, mx1, 1));
        mx1 = fmaxf(mx1, __shfl_xor_sync(0xffffffffu, mx1, 2));

        float mn0 = fmaxf(m0r, mx0), mn1 = fmaxf(m1r, mx1);
        float al0 = __expf(m0r - mn0), al1 = __expf(m1r - mn1);
        float su0 = 0.f, su1 = 0.f;
#pragma unroll
        for (int nf = 0; nf < 8; nf++) {
            float p0 = __expf(sacc[nf][0] - mn0);
            float p1 = __expf(sacc[nf][1] - mn0);
            float p2 = __expf(sacc[nf][2] - mn1);
            float p3 = __expf(sacc[nf][3] - mn1);
            sacc[nf][0] = p0; sacc[nf][1] = p1; sacc[nf][2] = p2; sacc[nf][3] = p3;
            su0 += p0 + p1; su1 += p2 + p3;
        }
        su0 += __shfl_xor_sync(0xffffffffu, su0, 1);
        su0 += __shfl_xor_sync(0xffffffffu, su0, 2);
        su1 += __shfl_xor_sync(0xffffffffu, su1, 1);
        su1 += __shfl_xor_sync(0xffffffffu, su1, 2);
        l0r = l0r * al0 + su0;  l1r = l1r * al1 + su1;
        m0r = mn0;              m1r = mn1;
#pragma unroll
        for (int nf = 0; nf < 16; nf++) {
            oacc[nf][0] *= al0; oacc[nf][1] *= al0;
            oacc[nf][2] *= al1; oacc[nf][3] *= al1;
        }

        const int pr = wr + g;
#pragma unroll
        for (int nf = 0; nf < 8; nf++) {
            int pc = nf * 8 + 2 * tg;
            sP[pr * SP_LD + pc]           = f2tf(sacc[nf][0]);
            sP[pr * SP_LD + pc + 1]       = f2tf(sacc[nf][1]);
            sP[(pr + 8) * SP_LD + pc]     = f2tf(sacc[nf][2]);
            sP[(pr + 8) * SP_LD + pc + 1] = f2tf(sacc[nf][3]);
        }
        __syncwarp();

#pragma unroll
        for (int kf = 0; kf < 8; kf++) {
            uint32_t a[4];
            ldm4(a, a_addr(sPb + (uint32_t)wr * (SP_LD * 4) + kf * 32, SP_LD * 4));
#pragma unroll
            for (int nfp = 0; nfp < 8; nfp++) {
                uint32_t bfr[4];
                ldm4(bfr, b_addr(sVtb + (uint32_t)(nfp * 16) * (SVT_LD * 4) + kf * 32,
                                 SVT_LD * 4));
                mma_tf32(oacc[2 * nfp],     a, bfr);
                mma_tf32(oacc[2 * nfp + 1], a, bfr + 2);
            }
        }
        __syncwarp();
    }

    // epilogue: y stored tf32-rounded
    float il0 = 1.0f / l0r, il1 = 1.0f / l1r;
    const int r0 = q0 + wr + g, r1 = r0 + 8;
#pragma unroll
    for (int nf = 0; nf < 16; nf++) {
        int c = nf * 8 + 2 * tg;
        yb[(size_t)r0 * C_SZ + c]     = __uint_as_float(f2tf(oacc[nf][0] * il0));
        yb[(size_t)r0 * C_SZ + c + 1] = __uint_as_float(f2tf(oacc[nf][1] * il0));
        yb[(size_t)r1 * C_SZ + c]     = __uint_as_float(f2tf(oacc[nf][2] * il1));
        yb[(size_t)r1 * C_SZ + c + 1] = __uint_as_float(f2tf(oacc[nf][3] * il1));
    }
}

// ---------------------------------------------------------------------------
// Launch
// ---------------------------------------------------------------------------
extern "C" void kernel_launch(void* const* d_in, const int* in_sizes, int n_in,
                              void* d_out, int out_size) {
    const float* x  = (const float*)d_in[0];
    const float* Wq = (const float*)d_in[1];
    const float* Wk = (const float*)d_in[2];
    const float* Wv = (const float*)d_in[3];
    const float* Wo = (const float*)d_in[4];
    float* out = (float*)d_out;

    float *gq, *gk, *gvt, *gy, *gxt, *gwqt, *gwkt, *gwvt, *gwot;
    cudaGetSymbolAddress((void**)&gq, g_q);
    cudaGetSymbolAddress((void**)&gk, g_k);
    cudaGetSymbolAddress((void**)&gvt, g_vt);
    cudaGetSymbolAddress((void**)&gy, g_y);
    cudaGetSymbolAddress((void**)&gxt, g_xt);
    cudaGetSymbolAddress((void**)&gwqt, g_wqt);
    cudaGetSymbolAddress((void**)&gwkt, g_wkt);
    cudaGetSymbolAddress((void**)&gwvt, g_wvt);
    cudaGetSymbolAddress((void**)&gwot, g_wot);

    cudaFuncSetAttribute(attn_kernel,
                         cudaFuncAttributeMaxDynamicSharedMemorySize,
                         ATTN_SMEM_BYTES);
    cudaFuncSetAttribute(gemm_nt,
                         cudaFuncAttributeMaxDynamicSharedMemorySize,
                         GEMM_SMEM_BYTES);

    init_invf<<<1, 64>>>();
    init_cs<<<T_SZ, 64>>>();

    // Pre-round operands to tf32 (one-time; numerics identical to per-use cvt)
    cvt_tf32<<<1024, 256>>>(x,  gxt,  MROWS * C_SZ / 4);
    cvt_tf32<<<1024, 256>>>(Wq, gwqt, C_SZ * C_SZ / 4);
    cvt_tf32<<<256,  256>>>(Wk, gwkt, KVD * C_SZ / 4);
    cvt_tf32<<<256,  256>>>(Wv, gwvt, KVD * C_SZ / 4);
    cvt_tf32<<<1024, 256>>>(Wo, gwot, C_SZ * C_SZ / 4);

    // Q projection
    gemm_nt<<<dim3(C_SZ / BN, MROWS / BM, 1), 256, GEMM_SMEM_BYTES>>>(
        gxt, gwqt, gwqt, gq, gq, C_SZ, C_SZ, 0);
    // K + V projections fused (z=0: K normal; z=1: V transposed tf32 epilogue)
    gemm_nt<<<dim3(KVD / BN, MROWS / BM, 2), 256, GEMM_SMEM_BYTES>>>(
        gxt, gwkt, gwvt, gk, gvt, KVD, C_SZ, MROWS);

    // RMSNorm + RoPE on q, k (writes tf32-rounded)
    {
        int total_warps = MROWS * NH + MROWS * NKV;
        int blocks = (total_warps + 7) / 8;
        normrope<<<blocks, 256>>>(gq, gk);
    }

    // Flash attention
    attn_kernel<<<dim3(T_SZ / 128, NH, B_SZ), 256, ATTN_SMEM_BYTES>>>(gq, gk, gvt, gy);

    // Output projection (gy already tf32-rounded)
    gemm_nt<<<dim3(C_SZ / BN, MROWS / BM, 1), 256, GEMM_SMEM_BYTES>>>(
        gy, gwot, gwot, out, out, C_SZ, C_SZ, 0);
}